// round 2
// baseline (speedup 1.0000x reference)
#include <cuda_runtime.h>

#define GRIDN 160
#define G3 (GRIDN*GRIDN*GRIDN)
#define NS 256
#define WIDTH 128
#define K0D 12
#define NEAR_T 0.2f
#define FAR_T 1.8f
#define ACT_SHIFT -4.59511985013459f

// Shared memory layout (floats)
#define OFF_W1   0            // 16384
#define OFF_H    16384        // 32768 (also reused as reduction buffer)
#define OFF_W0F  (16384+32768)            // 1536
#define OFF_W2   (OFF_W0F+1536)           // 384
#define OFF_H0   (OFF_W2+384)             // 128
#define OFF_B1   (OFF_H0+128)             // 128
#define OFF_P    (OFF_B1+128)             // 256
#define OFF_VB   (OFF_P+256)              // 32
#define SMEM_FLOATS (OFF_VB+32)
#define SMEM_BYTES (SMEM_FLOATS*4)

__global__ __launch_bounds__(256, 1)
void dvgo_fused_kernel(const float* __restrict__ ro, const float* __restrict__ rd,
                       const float* __restrict__ density, const float* __restrict__ k0,
                       const float* __restrict__ W0, const float* __restrict__ b0,
                       const float* __restrict__ W1, const float* __restrict__ b1,
                       const float* __restrict__ W2, const float* __restrict__ b2,
                       float* __restrict__ out)
{
    extern __shared__ float smem[];
    float* sW1  = smem + OFF_W1;
    float* sH   = smem + OFF_H;
    float* sW0f = smem + OFF_W0F;
    float* sW2  = smem + OFF_W2;
    float* sh0  = smem + OFF_H0;
    float* sb1  = smem + OFF_B1;
    float* sP   = smem + OFF_P;
    float* svb  = smem + OFF_VB;

    const int tid = threadIdx.x;
    const int ray = blockIdx.x;

    // ---- cooperative weight loads (visibility guaranteed by scan's syncthreads) ----
    {
        const float4* g = (const float4*)W1;
        float4* s = (float4*)sW1;
        #pragma unroll
        for (int i = 0; i < 16; ++i) s[tid + 256*i] = g[tid + 256*i];   // 4096 float4
    }
    {
        const float4* g = (const float4*)W0;      // rows 0..11 are the feat part (contiguous)
        float4* s = (float4*)sW0f;
        s[tid] = g[tid];                          // 256
        if (tid < 128) s[256 + tid] = g[256 + tid]; // +128 = 384 float4 = 1536 floats
    }
    if (tid < 96) ((float4*)sW2)[tid] = ((const float4*)W2)[tid];   // 384 floats
    if (tid < 128) sb1[tid] = b1[tid];

    const float ox = ro[3*ray+0], oy = ro[3*ray+1], oz = ro[3*ray+2];
    const float dx = rd[3*ray+0], dy = rd[3*ray+1], dz = rd[3*ray+2];

    // ---- view embedding (once per ray) ----
    if (tid == 0) {
        float inv = 1.0f / sqrtf(dx*dx + dy*dy + dz*dz);
        float v[3] = {dx*inv, dy*inv, dz*inv};
        svb[0] = v[0]; svb[1] = v[1]; svb[2] = v[2];
        #pragma unroll
        for (int i = 0; i < 3; ++i) {
            #pragma unroll
            for (int j = 0; j < 4; ++j) {
                float a = v[i] * (float)(1 << j);
                svb[3  + i*4 + j] = sinf(a);
                svb[15 + i*4 + j] = cosf(a);
            }
        }
    }

    // ---- sample point + trilinear setup ----
    const float tpar = NEAR_T + (FAR_T - NEAR_T) * ((float)tid * (1.0f/(float)(NS-1)));
    float px = ox + dx*tpar, py = oy + dy*tpar, pz = oz + dz*tpar;

    float gx = (px + 1.0f) * (0.5f * 159.0f);
    float gy = (py + 1.0f) * (0.5f * 159.0f);
    float gz = (pz + 1.0f) * (0.5f * 159.0f);
    gx = fminf(fmaxf(gx, 0.0f), 159.0f);
    gy = fminf(fmaxf(gy, 0.0f), 159.0f);
    gz = fminf(fmaxf(gz, 0.0f), 159.0f);
    int x0 = min((int)floorf(gx), 158);
    int y0 = min((int)floorf(gy), 158);
    int z0 = min((int)floorf(gz), 158);
    const float fx = gx - (float)x0;
    const float fy = gy - (float)y0;
    const float fz = gz - (float)z0;
    const int idx000 = (x0*GRIDN + y0)*GRIDN + z0;

    const float wx0 = 1.0f - fx, wy0 = 1.0f - fy, wz0 = 1.0f - fz;
    float w8[8];
    w8[0] = wx0*wy0*wz0; w8[1] = wx0*wy0*fz;
    w8[2] = wx0*fy*wz0;  w8[3] = wx0*fy*fz;
    w8[4] = fx*wy0*wz0;  w8[5] = fx*wy0*fz;
    w8[6] = fx*fy*wz0;   w8[7] = fx*fy*fz;
    const int offs[8] = {0, 1, GRIDN, GRIDN+1,
                         GRIDN*GRIDN, GRIDN*GRIDN+1, GRIDN*GRIDN+GRIDN, GRIDN*GRIDN+GRIDN+1};

    // ---- density -> alpha ----
    float sigma = 0.0f;
    {
        const float* g = density + idx000;
        #pragma unroll
        for (int c = 0; c < 8; ++c) sigma += w8[c] * __ldg(g + offs[c]);
    }
    const float e = expf(sigma + ACT_SHIFT);
    const float oneminus = 1.0f / sqrtf(1.0f + e);   // (1+e)^-0.5
    const float alpha = 1.0f - oneminus;
    const float sval = oneminus + 1e-10f;

    // ---- inclusive cumprod scan over samples (Hillis-Steele) ----
    sP[tid] = sval;
    __syncthreads();
    #pragma unroll
    for (int off = 1; off < NS; off <<= 1) {
        float cur = sP[tid];
        float pre = (tid >= off) ? sP[tid - off] : 1.0f;
        __syncthreads();
        sP[tid] = cur * pre;
        __syncthreads();
    }
    const float Texc = (tid == 0) ? 1.0f : sP[tid - 1];
    const float wgt  = alpha * Texc;
    const float ainv = sP[NS - 1];

    // ---- per-ray folded layer0 bias: h0v[j] = b0[j] + vemb . W0[12:39, j] ----
    if (tid < 128) {
        float acc = b0[tid];
        #pragma unroll
        for (int dd = 0; dd < 27; ++dd)
            acc += svb[dd] * __ldg(&W0[(12 + dd)*WIDTH + tid]);
        sh0[tid] = acc;
    }

    // ---- k0 trilinear gather (12 channels) ----
    float feat[K0D];
    #pragma unroll
    for (int c = 0; c < K0D; ++c) {
        const float* g = k0 + (size_t)c * G3 + idx000;
        float acc = 0.0f;
        #pragma unroll
        for (int cn = 0; cn < 8; ++cn) acc += w8[cn] * __ldg(g + offs[cn]);
        feat[c] = acc;
    }
    __syncthreads();   // sh0 + all smem weights ready

    // ---- layer 0: h1[j] = relu(h0v[j] + feat . W0f[:,j]) ; store [k][tid] ----
    for (int j = 0; j < WIDTH; j += 4) {
        float4 a = *(const float4*)(sh0 + j);
        #pragma unroll
        for (int k = 0; k < K0D; ++k) {
            const float f = feat[k];
            const float4 w = *(const float4*)(sW0f + k*WIDTH + j);
            a.x += f*w.x; a.y += f*w.y; a.z += f*w.z; a.w += f*w.w;
        }
        sH[(j+0)*256 + tid] = fmaxf(a.x, 0.0f);
        sH[(j+1)*256 + tid] = fmaxf(a.y, 0.0f);
        sH[(j+2)*256 + tid] = fmaxf(a.z, 0.0f);
        sH[(j+3)*256 + tid] = fmaxf(a.w, 0.0f);
    }
    // no cross-thread dependency on sH columns: each thread only reads its own column

    // ---- layer 1 (+ fused layer 2 accumulation) ----
    float rr = b2[0], gg = b2[1], bb = b2[2];
    for (int j = 0; j < WIDTH; j += 8) {
        float acc[8];
        #pragma unroll
        for (int q = 0; q < 8; ++q) acc[q] = sb1[j + q];
        #pragma unroll 4
        for (int k = 0; k < WIDTH; ++k) {
            const float h = sH[k*256 + tid];
            const float4 wA = *(const float4*)(sW1 + k*WIDTH + j);
            const float4 wB = *(const float4*)(sW1 + k*WIDTH + j + 4);
            acc[0] += h*wA.x; acc[1] += h*wA.y; acc[2] += h*wA.z; acc[3] += h*wA.w;
            acc[4] += h*wB.x; acc[5] += h*wB.y; acc[6] += h*wB.z; acc[7] += h*wB.w;
        }
        #pragma unroll
        for (int q = 0; q < 8; ++q) {
            const float hq = fmaxf(acc[q], 0.0f);
            rr += hq * sW2[(j+q)*3 + 0];
            gg += hq * sW2[(j+q)*3 + 1];
            bb += hq * sW2[(j+q)*3 + 2];
        }
    }
    rr = 1.0f / (1.0f + expf(-rr));
    gg = 1.0f / (1.0f + expf(-gg));
    bb = 1.0f / (1.0f + expf(-bb));

    // ---- weighted reduction over samples ----
    __syncthreads();               // done reading sH as h1; reuse as reduction buffer
    sH[tid]       = wgt * rr;
    sH[256 + tid] = wgt * gg;
    sH[512 + tid] = wgt * bb;
    __syncthreads();
    #pragma unroll
    for (int st = 128; st > 0; st >>= 1) {
        if (tid < st) {
            sH[tid]       += sH[tid + st];
            sH[256 + tid] += sH[256 + tid + st];
            sH[512 + tid] += sH[512 + tid + st];
        }
        __syncthreads();
    }
    if (tid == 0) {
        out[3*ray + 0] = sH[0]   + ainv;
        out[3*ray + 1] = sH[256] + ainv;
        out[3*ray + 2] = sH[512] + ainv;
    }
}

extern "C" void kernel_launch(void* const* d_in, const int* in_sizes, int n_in,
                              void* d_out, int out_size) {
    const float* ro      = (const float*)d_in[0];
    const float* rd      = (const float*)d_in[1];
    const float* density = (const float*)d_in[2];
    const float* k0      = (const float*)d_in[3];
    const float* W0      = (const float*)d_in[4];
    const float* b0      = (const float*)d_in[5];
    const float* W1      = (const float*)d_in[6];
    const float* b1      = (const float*)d_in[7];
    const float* W2      = (const float*)d_in[8];
    const float* b2      = (const float*)d_in[9];
    float* out = (float*)d_out;

    const int nrays = in_sizes[0] / 3;

    cudaFuncSetAttribute(dvgo_fused_kernel,
                         cudaFuncAttributeMaxDynamicSharedMemorySize, SMEM_BYTES);
    dvgo_fused_kernel<<<nrays, 256, SMEM_BYTES>>>(ro, rd, density, k0,
                                                  W0, b0, W1, b1, W2, b2, out);
}

// round 6
// speedup vs baseline: 2.1470x; 2.1470x over previous
#include <cuda_runtime.h>
#include <cuda_bf16.h>
#include <cstdint>

#define GRIDN 160
#define NS 256
#define WIDTH 128
#define K0D 12
#define NEAR_T 0.2f
#define FAR_T 1.8f
#define ACT_SHIFT -4.59511985013459f

// A/B rows padded to 136 bf16 = 272 bytes (16B-aligned, ldmatrix conflict-free)
#define ASTRIDE 272
#define A_REG   (256 * ASTRIDE)   // 69632
#define B_REG   (128 * ASTRIDE)   // 34816

// smem byte offsets
#define SM_A_HI  0
#define SM_A_LO  (A_REG)                  // 69632
#define SM_B_HI  (2*A_REG)                // 139264
#define SM_B_LO  (2*A_REG + B_REG)        // 174080
#define SM_W0F   (2*A_REG + 2*B_REG)      // 208896 (6144)
#define SM_W2    (SM_W0F + 6144)          // 215040 (1536)
#define SM_H0    (SM_W2 + 1536)           // 216576 (512)
#define SM_B1    (SM_H0 + 512)            // 217088 (512)
#define SM_P     (SM_B1 + 512)            // 217600 (1024)
#define SM_WGT   (SM_P + 1024)            // 218624 (1024)
#define SM_VB    (SM_WGT + 1024)          // 219648 (128)
#define SM_RED   (SM_VB + 128)            // 219776 (3072)
#define SMEM_BYTES (SM_RED + 3072)        // 222848

__device__ __align__(16) unsigned char g_W1B[2 * B_REG];   // hi then lo, [n][k] bf16, stride 272B

// Prep: B[n][k] = W1[k][n] split into bf16 hi/lo.
__global__ void prep_kernel(const float* __restrict__ W1) {
    int idx = blockIdx.x * blockDim.x + threadIdx.x;   // 16384
    int n = idx >> 7, k = idx & 127;
    float w = W1[k * WIDTH + n];
    __nv_bfloat16 hi = __float2bfloat16_rn(w);
    float rem = w - __bfloat162float(hi);
    __nv_bfloat16 lo = __float2bfloat16_rn(rem);
    *(__nv_bfloat16*)(g_W1B + n * ASTRIDE + k * 2)         = hi;
    *(__nv_bfloat16*)(g_W1B + B_REG + n * ASTRIDE + k * 2) = lo;
}

__device__ __forceinline__ void ldsm4(uint32_t* r, uint32_t addr) {
    asm volatile("ldmatrix.sync.aligned.m8n8.x4.shared.b16 {%0,%1,%2,%3}, [%4];"
        : "=r"(r[0]), "=r"(r[1]), "=r"(r[2]), "=r"(r[3]) : "r"(addr));
}

__device__ __forceinline__ void mma_bf16(float* c, const uint32_t* a, const uint32_t* b) {
    asm volatile(
        "mma.sync.aligned.m16n8k16.row.col.f32.bf16.bf16.f32 "
        "{%0,%1,%2,%3}, {%4,%5,%6,%7}, {%8,%9}, {%0,%1,%2,%3};"
        : "+f"(c[0]), "+f"(c[1]), "+f"(c[2]), "+f"(c[3])
        : "r"(a[0]), "r"(a[1]), "r"(a[2]), "r"(a[3]), "r"(b[0]), "r"(b[1]));
}

__global__ __launch_bounds__(256, 1)
void dvgo_mma_kernel(const float* __restrict__ ro, const float* __restrict__ rd,
                     const float* __restrict__ density, const float* __restrict__ k0,
                     const float* __restrict__ W0, const float* __restrict__ b0,
                     const float* __restrict__ b1,
                     const float* __restrict__ W2, const float* __restrict__ b2,
                     float* __restrict__ out)
{
    extern __shared__ __align__(16) char smem[];
    const uint32_t sbs = (uint32_t)__cvta_generic_to_shared(smem);
    const int tid = threadIdx.x;
    const int wid = tid >> 5;
    const int lane = tid & 31;
    const int ray = blockIdx.x;

    // ---- cooperative loads: W1 hi/lo (69632B), W0 feat rows, W2, b1 ----
    {
        const uint4* src = (const uint4*)g_W1B;
        uint4* dst = (uint4*)(smem + SM_B_HI);
        #pragma unroll
        for (int i = 0; i < 17; ++i) dst[tid + 256 * i] = src[tid + 256 * i];  // 4352 uint4
    }
    {
        const float4* g = (const float4*)W0;           // rows 0..11 contiguous: 384 float4
        float4* s = (float4*)(smem + SM_W0F);
        s[tid] = g[tid];
        if (tid < 128) s[256 + tid] = g[256 + tid];
    }
    if (tid < 96) ((float4*)(smem + SM_W2))[tid] = ((const float4*)W2)[tid];
    float* sb1 = (float*)(smem + SM_B1);
    if (tid < 128) sb1[tid] = b1[tid];

    const float ox = ro[3*ray+0], oy = ro[3*ray+1], oz = ro[3*ray+2];
    const float dx = rd[3*ray+0], dy = rd[3*ray+1], dz = rd[3*ray+2];

    // ---- view embedding (once per ray) ----
    float* svb = (float*)(smem + SM_VB);
    if (tid == 0) {
        float inv = 1.0f / sqrtf(dx*dx + dy*dy + dz*dz);
        float v[3] = {dx*inv, dy*inv, dz*inv};
        svb[0] = v[0]; svb[1] = v[1]; svb[2] = v[2];
        #pragma unroll
        for (int i = 0; i < 3; ++i)
            #pragma unroll
            for (int j = 0; j < 4; ++j) {
                float a = v[i] * (float)(1 << j);
                svb[3  + i*4 + j] = sinf(a);
                svb[15 + i*4 + j] = cosf(a);
            }
    }

    // ---- sample point + trilinear setup (thread = sample) ----
    const float tpar = NEAR_T + (FAR_T - NEAR_T) * ((float)tid * (1.0f/(float)(NS-1)));
    float gx = (ox + dx*tpar + 1.0f) * (0.5f * 159.0f);
    float gy = (oy + dy*tpar + 1.0f) * (0.5f * 159.0f);
    float gz = (oz + dz*tpar + 1.0f) * (0.5f * 159.0f);
    gx = fminf(fmaxf(gx, 0.0f), 159.0f);
    gy = fminf(fmaxf(gy, 0.0f), 159.0f);
    gz = fminf(fmaxf(gz, 0.0f), 159.0f);
    int x0 = min((int)floorf(gx), 158);
    int y0 = min((int)floorf(gy), 158);
    int z0 = min((int)floorf(gz), 158);
    const float fx = gx - (float)x0, fy = gy - (float)y0, fz = gz - (float)z0;
    const int idx000 = (x0*GRIDN + y0)*GRIDN + z0;
    const float wx0 = 1.0f-fx, wy0 = 1.0f-fy, wz0 = 1.0f-fz;
    float w8[8];
    w8[0]=wx0*wy0*wz0; w8[1]=wx0*wy0*fz; w8[2]=wx0*fy*wz0; w8[3]=wx0*fy*fz;
    w8[4]=fx*wy0*wz0;  w8[5]=fx*wy0*fz;  w8[6]=fx*fy*wz0;  w8[7]=fx*fy*fz;
    const int offs[8] = {0, 1, GRIDN, GRIDN+1,
                         GRIDN*GRIDN, GRIDN*GRIDN+1, GRIDN*GRIDN+GRIDN, GRIDN*GRIDN+GRIDN+1};

    // ---- density -> alpha ----
    float sigma = 0.0f;
    {
        const float* g = density + idx000;
        #pragma unroll
        for (int c = 0; c < 8; ++c) sigma += w8[c] * __ldg(g + offs[c]);
    }
    const float e = expf(sigma + ACT_SHIFT);
    const float oneminus = 1.0f / sqrtf(1.0f + e);   // (1+e)^-0.5
    const float alpha = 1.0f - oneminus;

    // ---- inclusive cumprod scan (also fences the cooperative loads) ----
    float* sP = (float*)(smem + SM_P);
    sP[tid] = oneminus + 1e-10f;
    __syncthreads();
    #pragma unroll
    for (int off = 1; off < NS; off <<= 1) {
        float cur = sP[tid];
        float pre = (tid >= off) ? sP[tid - off] : 1.0f;
        __syncthreads();
        sP[tid] = cur * pre;
        __syncthreads();
    }
    const float Texc = (tid == 0) ? 1.0f : sP[tid - 1];
    float* sWgt = (float*)(smem + SM_WGT);
    sWgt[tid] = alpha * Texc;
    const float ainv = sP[NS - 1];

    // ---- per-ray folded layer0 bias: h0v[j] = b0[j] + vemb . W0[12:39, j] ----
    float* sh0 = (float*)(smem + SM_H0);
    if (tid < 128) {
        float acc = b0[tid];
        #pragma unroll
        for (int dd = 0; dd < 27; ++dd)
            acc += svb[dd] * __ldg(&W0[(12 + dd)*WIDTH + tid]);
        sh0[tid] = acc;
    }

    // ---- k0 trilinear gather (12 channels) ----
    float feat[K0D];
    #pragma unroll
    for (int c = 0; c < K0D; ++c) {
        const float* g = k0 + (size_t)c * (GRIDN*GRIDN*GRIDN) + idx000;
        float acc = 0.0f;
        #pragma unroll
        for (int cn = 0; cn < 8; ++cn) acc += w8[cn] * __ldg(g + offs[cn]);
        feat[c] = acc;
    }
    __syncthreads();   // sh0 / sW0f / sWgt ready

    // ---- layer 0 + relu + hi/lo bf16 split -> A rows (row = sample = tid) ----
    const float* sW0f = (const float*)(smem + SM_W0F);
    {
        char* arowHi = smem + SM_A_HI + tid * ASTRIDE;
        char* arowLo = smem + SM_A_LO + tid * ASTRIDE;
        for (int j = 0; j < WIDTH; j += 8) {
            float a[8];
            {
                float4 a0 = *(const float4*)(sh0 + j);
                float4 a1 = *(const float4*)(sh0 + j + 4);
                a[0]=a0.x; a[1]=a0.y; a[2]=a0.z; a[3]=a0.w;
                a[4]=a1.x; a[5]=a1.y; a[6]=a1.z; a[7]=a1.w;
            }
            #pragma unroll
            for (int c = 0; c < K0D; ++c) {
                const float f = feat[c];
                const float4 wA = *(const float4*)(sW0f + c*WIDTH + j);
                const float4 wB = *(const float4*)(sW0f + c*WIDTH + j + 4);
                a[0]+=f*wA.x; a[1]+=f*wA.y; a[2]+=f*wA.z; a[3]+=f*wA.w;
                a[4]+=f*wB.x; a[5]+=f*wB.y; a[6]+=f*wB.z; a[7]+=f*wB.w;
            }
            uint32_t hi[4], lo[4];
            #pragma unroll
            for (int q = 0; q < 4; ++q) {
                float v0 = fmaxf(a[2*q],   0.0f);
                float v1 = fmaxf(a[2*q+1], 0.0f);
                __nv_bfloat16 h0 = __float2bfloat16_rn(v0);
                __nv_bfloat16 h1 = __float2bfloat16_rn(v1);
                __nv_bfloat16 g0 = __float2bfloat16_rn(v0 - __bfloat162float(h0));
                __nv_bfloat16 g1 = __float2bfloat16_rn(v1 - __bfloat162float(h1));
                hi[q] = (uint32_t)__bfloat16_as_ushort(h0) | ((uint32_t)__bfloat16_as_ushort(h1) << 16);
                lo[q] = (uint32_t)__bfloat16_as_ushort(g0) | ((uint32_t)__bfloat16_as_ushort(g1) << 16);
            }
            *(uint4*)(arowHi + j*2) = make_uint4(hi[0],hi[1],hi[2],hi[3]);
            *(uint4*)(arowLo + j*2) = make_uint4(lo[0],lo[1],lo[2],lo[3]);
        }
    }
    __syncthreads();

    // ---- layer 1 warp GEMM: D[32x128] = A @ W1, 3-product bf16 split ----
    // A frag addr: rows wid*32 + mt*16 + (lane&15), +16B for k8-15 half
    const uint32_t aAddr = sbs + SM_A_HI
        + (uint32_t)(wid*32 + (lane & 15)) * ASTRIDE + (uint32_t)((lane >> 4) * 16);
    // B frag addr (two n-tiles per ldsm4): n = nt2*16 + (lane&7) + ((lane>>4)&1)*8, +16B for k8-15
    const uint32_t bAddr = sbs + SM_B_HI
        + (uint32_t)((lane & 7) + ((lane >> 4) & 1) * 8) * ASTRIDE
        + (uint32_t)(((lane >> 3) & 1) * 16);

    float acc[2][16][4];
    #pragma unroll
    for (int mt = 0; mt < 2; ++mt)
        #pragma unroll
        for (int nt = 0; nt < 16; ++nt)
            #pragma unroll
            for (int q = 0; q < 4; ++q) acc[mt][nt][q] = 0.0f;

    #pragma unroll 1
    for (int p = 0; p < 3; ++p) {
        const uint32_t aBase = aAddr + (p == 2 ? (uint32_t)A_REG : 0u);   // A lo on product 2
        const uint32_t bBase = bAddr + (p == 1 ? (uint32_t)B_REG : 0u);   // B lo on product 1
        #pragma unroll
        for (int k = 0; k < 8; ++k) {
            uint32_t a0[4], a1[4];
            ldsm4(a0, aBase + (uint32_t)(k*32));
            ldsm4(a1, aBase + (uint32_t)(k*32) + 16u*ASTRIDE);
            #pragma unroll
            for (int nt2 = 0; nt2 < 8; ++nt2) {
                uint32_t b[4];
                ldsm4(b, bBase + (uint32_t)(k*32) + (uint32_t)nt2 * (16u*ASTRIDE));
                mma_bf16(acc[0][2*nt2],     a0, b);
                mma_bf16(acc[0][2*nt2 + 1], a0, b + 2);
                mma_bf16(acc[1][2*nt2],     a1, b);
                mma_bf16(acc[1][2*nt2 + 1], a1, b + 2);
            }
        }
    }

    // ---- epilogue on fragments: +b1, relu, .W2 -> per-row rgb partials ----
    const float* sW2 = (const float*)(smem + SM_W2);
    float rsum[2][2][3];
    #pragma unroll
    for (int mt = 0; mt < 2; ++mt)
        #pragma unroll
        for (int rh = 0; rh < 2; ++rh)
            #pragma unroll
            for (int c = 0; c < 3; ++c) rsum[mt][rh][c] = 0.0f;

    #pragma unroll
    for (int mt = 0; mt < 2; ++mt)
        #pragma unroll
        for (int nt = 0; nt < 16; ++nt) {
            const int c0 = nt*8 + 2*(lane & 3);
            const float bA = sb1[c0], bB = sb1[c0+1];
            const float h00 = fmaxf(acc[mt][nt][0] + bA, 0.0f);
            const float h01 = fmaxf(acc[mt][nt][1] + bB, 0.0f);
            const float h10 = fmaxf(acc[mt][nt][2] + bA, 0.0f);
            const float h11 = fmaxf(acc[mt][nt][3] + bB, 0.0f);
            #pragma unroll
            for (int c = 0; c < 3; ++c) {
                const float wA = sW2[c0*3 + c], wB = sW2[c0*3 + 3 + c];
                rsum[mt][0][c] += h00*wA + h01*wB;
                rsum[mt][1][c] += h10*wA + h11*wB;
            }
        }
    // reduce the 4-lane row group
    #pragma unroll
    for (int mt = 0; mt < 2; ++mt)
        #pragma unroll
        for (int rh = 0; rh < 2; ++rh)
            #pragma unroll
            for (int c = 0; c < 3; ++c) {
                float v = rsum[mt][rh][c];
                v += __shfl_xor_sync(0xFFFFFFFF, v, 1);
                v += __shfl_xor_sync(0xFFFFFFFF, v, 2);
                rsum[mt][rh][c] = v;
            }

    float* red = (float*)(smem + SM_RED);
    {
        const float b20 = __ldg(b2), b21 = __ldg(b2+1), b22 = __ldg(b2+2);
        if ((lane & 3) == 0) {
            #pragma unroll
            for (int mt = 0; mt < 2; ++mt)
                #pragma unroll
                for (int rh = 0; rh < 2; ++rh) {
                    const int s = wid*32 + mt*16 + rh*8 + (lane >> 2);
                    const float w = sWgt[s];
                    const float vr = 1.0f/(1.0f + expf(-(rsum[mt][rh][0] + b20)));
                    const float vg = 1.0f/(1.0f + expf(-(rsum[mt][rh][1] + b21)));
                    const float vb = 1.0f/(1.0f + expf(-(rsum[mt][rh][2] + b22)));
                    red[s]       = w * vr;
                    red[256 + s] = w * vg;
                    red[512 + s] = w * vb;
                }
        }
    }
    __syncthreads();
    #pragma unroll
    for (int st = 128; st > 0; st >>= 1) {
        if (tid < st) {
            red[tid]       += red[tid + st];
            red[256 + tid] += red[256 + tid + st];
            red[512 + tid] += red[512 + tid + st];
        }
        __syncthreads();
    }
    if (tid == 0) {
        out[3*ray + 0] = red[0]   + ainv;
        out[3*ray + 1] = red[256] + ainv;
        out[3*ray + 2] = red[512] + ainv;
    }
}

extern "C" void kernel_launch(void* const* d_in, const int* in_sizes, int n_in,
                              void* d_out, int out_size) {
    const float* ro      = (const float*)d_in[0];
    const float* rd      = (const float*)d_in[1];
    const float* density = (const float*)d_in[2];
    const float* k0      = (const float*)d_in[3];
    const float* W0      = (const float*)d_in[4];
    const float* b0      = (const float*)d_in[5];
    const float* W1      = (const float*)d_in[6];
    const float* b1      = (const float*)d_in[7];
    const float* W2      = (const float*)d_in[8];
    const float* b2      = (const float*)d_in[9];
    float* out = (float*)d_out;

    const int nrays = in_sizes[0] / 3;

    prep_kernel<<<64, 256>>>(W1);

    cudaFuncSetAttribute(dvgo_mma_kernel,
                         cudaFuncAttributeMaxDynamicSharedMemorySize, SMEM_BYTES);
    dvgo_mma_kernel<<<nrays, 256, SMEM_BYTES>>>(ro, rd, density, k0,
                                                W0, b0, b1, W2, b2, out);
}

// round 9
// speedup vs baseline: 4.8971x; 2.2809x over previous
#include <cuda_runtime.h>
#include <cuda_fp16.h>
#include <cstdint>

#define GRIDN 160
#define NS 256
#define WIDTH 128
#define K0D 12
#define NEAR_T 0.2f
#define FAR_T 1.8f
#define ACT_SHIFT -4.59511985013459f

// row strides chosen conflict-free for ldmatrix: words%32 == 4 (272B) / 12 (48B)
#define ASTRIDE1 272     // A1/B1 rows: 128 fp16 = 256B data + pad
#define ASTRIDE0 48      // A0/B0 rows: 16 fp16 = 32B data + pad
#define B1_BYTES (128 * ASTRIDE1)   // 34816
#define A1_BYTES (256 * ASTRIDE1)   // 69632
#define A0_BYTES (256 * ASTRIDE0)   // 12288
#define B0_BYTES (128 * ASTRIDE0)   // 6144

// smem byte offsets
#define SM_B1   0
#define SM_A1   (B1_BYTES)                         // 34816
#define SM_A0   (SM_A1 + A1_BYTES)                 // 104448
#define SM_B0   (SM_A0 + A0_BYTES)                 // 116736
#define SM_W2   (SM_B0 + B0_BYTES)                 // 122880 (1536)
#define SM_H0   (SM_W2 + 1536)                     // 124416 (512)
#define SM_BB1  (SM_H0 + 512)                      // 124928 (512)
#define SM_WGT  (SM_BB1 + 512)                     // 125440 (1024)
#define SM_VB   (SM_WGT + 1024)                    // 126464 (128)
#define SM_WS   (SM_VB + 128)                      // 126592 (64: scan)
#define SM_RED  (SM_WS + 64)                       // 126656 (96)
#define SMEM_BYTES 126976

__device__ __align__(16) unsigned char g_B1[B1_BYTES];  // W1^T fp16 [n][k], stride 272
__device__ __align__(16) unsigned char g_B0[B0_BYTES];  // W0feat^T fp16 [n][k16], stride 48

// Prep: B1[n][k] = W1[k][n]; B0[n][k] = W0[k][n] (k<12) else 0.
__global__ void prep_kernel(const float* __restrict__ W1, const float* __restrict__ W0) {
    int idx = blockIdx.x * blockDim.x + threadIdx.x;   // 16384
    {
        int n = idx >> 7, k = idx & 127;
        *(__half*)(g_B1 + n * ASTRIDE1 + k * 2) = __float2half_rn(W1[k * WIDTH + n]);
    }
    if (idx < 2048) {
        int n = idx >> 4, k = idx & 15;
        float v = (k < K0D) ? W0[k * WIDTH + n] : 0.0f;
        *(__half*)(g_B0 + n * ASTRIDE0 + k * 2) = __float2half_rn(v);
    }
}

__device__ __forceinline__ void ldsm4(uint32_t* r, uint32_t addr) {
    asm volatile("ldmatrix.sync.aligned.m8n8.x4.shared.b16 {%0,%1,%2,%3}, [%4];"
        : "=r"(r[0]), "=r"(r[1]), "=r"(r[2]), "=r"(r[3]) : "r"(addr));
}

__device__ __forceinline__ void mma_fp16(float* c, const uint32_t* a, const uint32_t* b) {
    asm volatile(
        "mma.sync.aligned.m16n8k16.row.col.f32.f16.f16.f32 "
        "{%0,%1,%2,%3}, {%4,%5,%6,%7}, {%8,%9}, {%0,%1,%2,%3};"
        : "+f"(c[0]), "+f"(c[1]), "+f"(c[2]), "+f"(c[3])
        : "r"(a[0]), "r"(a[1]), "r"(a[2]), "r"(a[3]), "r"(b[0]), "r"(b[1]));
}

__device__ __forceinline__ uint32_t packh2(float a, float b) {
    __half2 h = __floats2half2_rn(a, b);
    return *(uint32_t*)&h;
}

__global__ __launch_bounds__(256, 1)
void dvgo_fp16_kernel(const float* __restrict__ ro, const float* __restrict__ rd,
                      const float* __restrict__ density, const float* __restrict__ k0,
                      const float* __restrict__ W0, const float* __restrict__ b0,
                      const float* __restrict__ b1,
                      const float* __restrict__ W2, const float* __restrict__ b2,
                      float* __restrict__ out)
{
    extern __shared__ __align__(16) char smem[];
    const uint32_t sbs = (uint32_t)__cvta_generic_to_shared(smem);
    const int tid = threadIdx.x;
    const int wid = tid >> 5;
    const int lane = tid & 31;
    const int ray = blockIdx.x;

    // ---- cooperative loads: B1 (34816B), B0 (6144B), W2, b1 ----
    {
        const uint4* src = (const uint4*)g_B1;
        uint4* dst = (uint4*)(smem + SM_B1);
        #pragma unroll
        for (int i = 0; i < 8; ++i) dst[tid + 256 * i] = src[tid + 256 * i];   // 2048
        if (tid < 128) dst[2048 + tid] = src[2048 + tid];                       // 2176 total
    }
    {
        const uint4* src = (const uint4*)g_B0;
        uint4* dst = (uint4*)(smem + SM_B0);
        dst[tid] = src[tid];
        if (tid < 128) dst[256 + tid] = src[256 + tid];                         // 384 total
    }
    if (tid < 96) ((float4*)(smem + SM_W2))[tid] = ((const float4*)W2)[tid];
    float* sb1 = (float*)(smem + SM_BB1);
    if (tid < 128) sb1[tid] = b1[tid];

    const float ox = ro[3*ray+0], oy = ro[3*ray+1], oz = ro[3*ray+2];
    const float dx = rd[3*ray+0], dy = rd[3*ray+1], dz = rd[3*ray+2];

    // ---- view embedding (once per ray) ----
    float* svb = (float*)(smem + SM_VB);
    if (tid == 0) {
        float inv = 1.0f / sqrtf(dx*dx + dy*dy + dz*dz);
        float v[3] = {dx*inv, dy*inv, dz*inv};
        svb[0] = v[0]; svb[1] = v[1]; svb[2] = v[2];
        #pragma unroll
        for (int i = 0; i < 3; ++i)
            #pragma unroll
            for (int j = 0; j < 4; ++j) {
                float a = v[i] * (float)(1 << j);
                svb[3  + i*4 + j] = sinf(a);
                svb[15 + i*4 + j] = cosf(a);
            }
    }

    // ---- sample point + trilinear setup (thread = sample) ----
    const float tpar = NEAR_T + (FAR_T - NEAR_T) * ((float)tid * (1.0f/(float)(NS-1)));
    float gx = (ox + dx*tpar + 1.0f) * (0.5f * 159.0f);
    float gy = (oy + dy*tpar + 1.0f) * (0.5f * 159.0f);
    float gz = (oz + dz*tpar + 1.0f) * (0.5f * 159.0f);
    gx = fminf(fmaxf(gx, 0.0f), 159.0f);
    gy = fminf(fmaxf(gy, 0.0f), 159.0f);
    gz = fminf(fmaxf(gz, 0.0f), 159.0f);
    int x0 = min((int)floorf(gx), 158);
    int y0 = min((int)floorf(gy), 158);
    int z0 = min((int)floorf(gz), 158);
    const float fx = gx - (float)x0, fy = gy - (float)y0, fz = gz - (float)z0;
    const int idx000 = (x0*GRIDN + y0)*GRIDN + z0;
    const float wx0 = 1.0f-fx, wy0 = 1.0f-fy, wz0 = 1.0f-fz;
    float w8[8];
    w8[0]=wx0*wy0*wz0; w8[1]=wx0*wy0*fz; w8[2]=wx0*fy*wz0; w8[3]=wx0*fy*fz;
    w8[4]=fx*wy0*wz0;  w8[5]=fx*wy0*fz;  w8[6]=fx*fy*wz0;  w8[7]=fx*fy*fz;
    const int offs[8] = {0, 1, GRIDN, GRIDN+1,
                         GRIDN*GRIDN, GRIDN*GRIDN+1, GRIDN*GRIDN+GRIDN, GRIDN*GRIDN+GRIDN+1};

    // ---- density -> alpha ----
    float sigma = 0.0f;
    {
        const float* g = density + idx000;
        #pragma unroll
        for (int c = 0; c < 8; ++c) sigma += w8[c] * __ldg(g + offs[c]);
    }
    const float e = expf(sigma + ACT_SHIFT);
    const float oneminus = 1.0f / sqrtf(1.0f + e);   // (1+e)^-0.5
    const float alpha = 1.0f - oneminus;

    // ---- inclusive cumprod scan: shfl warp scan + cross-warp (2 barriers) ----
    float* sWs = (float*)(smem + SM_WS);     // [0..7] warp totals, [8..15] inclusive
    float val = oneminus + 1e-10f;
    #pragma unroll
    for (int d = 1; d < 32; d <<= 1) {
        float p = __shfl_up_sync(0xFFFFFFFF, val, d);
        if (lane >= d) val *= p;
    }
    if (lane == 31) sWs[wid] = val;
    __syncthreads();                          // also fences cooperative loads
    if (tid < 8) {
        float w = sWs[tid];
        #pragma unroll
        for (int d = 1; d < 8; d <<= 1) {
            float p = __shfl_up_sync(0xFF, w, d);
            if (tid >= d) w *= p;
        }
        sWs[8 + tid] = w;
    }
    __syncthreads();
    const float pref = (wid == 0) ? 1.0f : sWs[8 + wid - 1];
    const float ainv = sWs[15];
    float Texc;
    {
        float incl = pref * val;
        float p = __shfl_up_sync(0xFFFFFFFF, incl, 1);
        Texc = (lane == 0) ? pref : p;
    }
    float* sWgt = (float*)(smem + SM_WGT);
    sWgt[tid] = alpha * Texc;

    // ---- per-ray folded layer0 bias: h0v[j] = b0[j] + vemb . W0[12:39, j] ----
    float* sh0 = (float*)(smem + SM_H0);
    if (tid < 128) {
        float acc = b0[tid];
        #pragma unroll
        for (int dd = 0; dd < 27; ++dd)
            acc += svb[dd] * __ldg(&W0[(12 + dd)*WIDTH + tid]);
        sh0[tid] = acc;
    }

    // ---- k0 trilinear gather (12 channels) -> A0 row (fp16, k pad to 16) ----
    {
        float feat[K0D];
        #pragma unroll
        for (int c = 0; c < K0D; ++c) {
            const float* g = k0 + (size_t)c * (GRIDN*GRIDN*GRIDN) + idx000;
            float acc = 0.0f;
            #pragma unroll
            for (int cn = 0; cn < 8; ++cn) acc += w8[cn] * __ldg(g + offs[cn]);
            feat[c] = acc;
        }
        uint32_t pk[8];
        #pragma unroll
        for (int q = 0; q < 6; ++q) pk[q] = packh2(feat[2*q], feat[2*q+1]);
        pk[6] = 0u; pk[7] = 0u;
        char* arow = smem + SM_A0 + tid * ASTRIDE0;
        *(uint4*)(arow)      = make_uint4(pk[0], pk[1], pk[2], pk[3]);
        *(uint4*)(arow + 16) = make_uint4(pk[4], pk[5], pk[6], pk[7]);
    }
    __syncthreads();   // sh0, A0 ready for all

    float acc[2][16][4];

    // ---- GEMM0: [256x16] feat @ [16x128] W0f -> fragments ----
    {
        const uint32_t aAddr = sbs + SM_A0
            + (uint32_t)(wid*32 + (lane & 15)) * ASTRIDE0 + (uint32_t)((lane >> 4) * 16);
        const uint32_t bAddr = sbs + SM_B0
            + (uint32_t)((lane & 7) + ((lane >> 4) & 1) * 8) * ASTRIDE0
            + (uint32_t)(((lane >> 3) & 1) * 16);
        #pragma unroll
        for (int mt = 0; mt < 2; ++mt)
            #pragma unroll
            for (int nt = 0; nt < 16; ++nt)
                #pragma unroll
                for (int q = 0; q < 4; ++q) acc[mt][nt][q] = 0.0f;
        uint32_t a0[4], a1[4];
        ldsm4(a0, aAddr);
        ldsm4(a1, aAddr + 16u * ASTRIDE0);
        #pragma unroll
        for (int nt2 = 0; nt2 < 8; ++nt2) {
            uint32_t b[4];
            ldsm4(b, bAddr + (uint32_t)nt2 * (16u * ASTRIDE0));
            mma_fp16(acc[0][2*nt2],     a0, b);
            mma_fp16(acc[0][2*nt2 + 1], a0, b + 2);
            mma_fp16(acc[1][2*nt2],     a1, b);
            mma_fp16(acc[1][2*nt2 + 1], a1, b + 2);
        }
    }

    // ---- epilogue0: +h0v, relu, fp16 pack -> A1 rows (same-warp rows) ----
    {
        const int rbase = wid*32 + (lane >> 2);
        #pragma unroll
        for (int mt = 0; mt < 2; ++mt)
            #pragma unroll
            for (int nt = 0; nt < 16; ++nt) {
                const int c0 = nt*8 + 2*(lane & 3);
                const float2 hb = *(const float2*)(sh0 + c0);
                const int r0 = rbase + mt*16;
                const uint32_t p0 = packh2(fmaxf(acc[mt][nt][0] + hb.x, 0.0f),
                                           fmaxf(acc[mt][nt][1] + hb.y, 0.0f));
                const uint32_t p1 = packh2(fmaxf(acc[mt][nt][2] + hb.x, 0.0f),
                                           fmaxf(acc[mt][nt][3] + hb.y, 0.0f));
                *(uint32_t*)(smem + SM_A1 + r0 * ASTRIDE1 + c0*2)            = p0;
                *(uint32_t*)(smem + SM_A1 + (r0 + 8) * ASTRIDE1 + c0*2)      = p1;
            }
    }
    __syncwarp();   // A1 rows are produced and consumed by the same warp

    // ---- GEMM1: [32x128] h @ [128x128] W1 per warp, single fp16 product ----
    {
        const uint32_t aAddr = sbs + SM_A1
            + (uint32_t)(wid*32 + (lane & 15)) * ASTRIDE1 + (uint32_t)((lane >> 4) * 16);
        const uint32_t bAddr = sbs + SM_B1
            + (uint32_t)((lane & 7) + ((lane >> 4) & 1) * 8) * ASTRIDE1
            + (uint32_t)(((lane >> 3) & 1) * 16);
        #pragma unroll
        for (int mt = 0; mt < 2; ++mt)
            #pragma unroll
            for (int nt = 0; nt < 16; ++nt)
                #pragma unroll
                for (int q = 0; q < 4; ++q) acc[mt][nt][q] = 0.0f;
        #pragma unroll
        for (int k = 0; k < 8; ++k) {
            uint32_t a0[4], a1[4];
            ldsm4(a0, aAddr + (uint32_t)(k*32));
            ldsm4(a1, aAddr + (uint32_t)(k*32) + 16u * ASTRIDE1);
            #pragma unroll
            for (int nt2 = 0; nt2 < 8; ++nt2) {
                uint32_t b[4];
                ldsm4(b, bAddr + (uint32_t)(k*32) + (uint32_t)nt2 * (16u * ASTRIDE1));
                mma_fp16(acc[0][2*nt2],     a0, b);
                mma_fp16(acc[0][2*nt2 + 1], a0, b + 2);
                mma_fp16(acc[1][2*nt2],     a1, b);
                mma_fp16(acc[1][2*nt2 + 1], a1, b + 2);
            }
        }
    }

    // ---- epilogue1: +b1, relu, .W2 -> per-row rgb partials ----
    const float* sW2 = (const float*)(smem + SM_W2);
    float rsum[2][2][3];
    #pragma unroll
    for (int mt = 0; mt < 2; ++mt)
        #pragma unroll
        for (int rh = 0; rh < 2; ++rh)
            #pragma unroll
            for (int c = 0; c < 3; ++c) rsum[mt][rh][c] = 0.0f;

    #pragma unroll
    for (int mt = 0; mt < 2; ++mt)
        #pragma unroll
        for (int nt = 0; nt < 16; ++nt) {
            const int c0 = nt*8 + 2*(lane & 3);
            const float bA = sb1[c0], bB = sb1[c0+1];
            const float h00 = fmaxf(acc[mt][nt][0] + bA, 0.0f);
            const float h01 = fmaxf(acc[mt][nt][1] + bB, 0.0f);
            const float h10 = fmaxf(acc[mt][nt][2] + bA, 0.0f);
            const float h11 = fmaxf(acc[mt][nt][3] + bB, 0.0f);
            #pragma unroll
            for (int c = 0; c < 3; ++c) {
                const float wA = sW2[c0*3 + c], wB = sW2[c0*3 + 3 + c];
                rsum[mt][0][c] += h00*wA + h01*wB;
                rsum[mt][1][c] += h10*wA + h11*wB;
            }
        }
    // reduce the 4-lane row group
    #pragma unroll
    for (int mt = 0; mt < 2; ++mt)
        #pragma unroll
        for (int rh = 0; rh < 2; ++rh)
            #pragma unroll
            for (int c = 0; c < 3; ++c) {
                float v = rsum[mt][rh][c];
                v += __shfl_xor_sync(0xFFFFFFFF, v, 1);
                v += __shfl_xor_sync(0xFFFFFFFF, v, 2);
                rsum[mt][rh][c] = v;
            }

    // ---- sigmoid, weight, warp-level reduce (1 barrier total) ----
    float pr = 0.0f, pg = 0.0f, pb = 0.0f;
    {
        const float b20 = __ldg(b2), b21 = __ldg(b2+1), b22 = __ldg(b2+2);
        if ((lane & 3) == 0) {
            #pragma unroll
            for (int mt = 0; mt < 2; ++mt)
                #pragma unroll
                for (int rh = 0; rh < 2; ++rh) {
                    const int s = wid*32 + mt*16 + rh*8 + (lane >> 2);
                    const float w = sWgt[s];
                    pr += w * (1.0f/(1.0f + expf(-(rsum[mt][rh][0] + b20))));
                    pg += w * (1.0f/(1.0f + expf(-(rsum[mt][rh][1] + b21))));
                    pb += w * (1.0f/(1.0f + expf(-(rsum[mt][rh][2] + b22))));
                }
        }
    }
    #pragma unroll
    for (int d = 4; d < 32; d <<= 1) {
        pr += __shfl_xor_sync(0xFFFFFFFF, pr, d);
        pg += __shfl_xor_sync(0xFFFFFFFF, pg, d);
        pb += __shfl_xor_sync(0xFFFFFFFF, pb, d);
    }
    float* red = (float*)(smem + SM_RED);
    if (lane == 0) {
        red[wid*3 + 0] = pr;
        red[wid*3 + 1] = pg;
        red[wid*3 + 2] = pb;
    }
    __syncthreads();
    if (tid == 0) {
        float r = ainv, g = ainv, b = ainv;
        #pragma unroll
        for (int w = 0; w < 8; ++w) {
            r += red[w*3 + 0];
            g += red[w*3 + 1];
            b += red[w*3 + 2];
        }
        out[3*ray + 0] = r;
        out[3*ray + 1] = g;
        out[3*ray + 2] = b;
    }
}

extern "C" void kernel_launch(void* const* d_in, const int* in_sizes, int n_in,
                              void* d_out, int out_size) {
    const float* ro      = (const float*)d_in[0];
    const float* rd      = (const float*)d_in[1];
    const float* density = (const float*)d_in[2];
    const float* k0      = (const float*)d_in[3];
    const float* W0      = (const float*)d_in[4];
    const float* b0      = (const float*)d_in[5];
    const float* W1      = (const float*)d_in[6];
    const float* b1      = (const float*)d_in[7];
    const float* W2      = (const float*)d_in[8];
    const float* b2      = (const float*)d_in[9];
    float* out = (float*)d_out;

    const int nrays = in_sizes[0] / 3;

    prep_kernel<<<64, 256>>>(W1, W0);

    cudaFuncSetAttribute(dvgo_fp16_kernel,
                         cudaFuncAttributeMaxDynamicSharedMemorySize, SMEM_BYTES);
    dvgo_fp16_kernel<<<nrays, 256, SMEM_BYTES>>>(ro, rd, density, k0,
                                                 W0, b0, b1, W2, b2, out);
}

// round 14
// speedup vs baseline: 6.1562x; 1.2571x over previous
#include <cuda_runtime.h>
#include <cuda_fp16.h>
#include <cstdint>

#define GRIDN 160
#define NS 256
#define WIDTH 128
#define K0D 12
#define NEAR_T 0.2f
#define FAR_T 1.8f
#define ACT_SHIFT -4.59511985013459f
#define NBLOCKS 296

// row strides conflict-free for ldmatrix: words%32 == 4 (272B) / 12 (48B)
#define ASTRIDE1 272
#define ASTRIDE0 48
#define B1_BYTES (128 * ASTRIDE1)   // 34816
#define A0_BYTES (256 * ASTRIDE0)   // 12288
#define B0_BYTES (128 * ASTRIDE0)   // 6144

// smem byte offsets
#define SM_B1   0
#define SM_B0   (B1_BYTES)                 // 34816
#define SM_A0   (SM_B0 + B0_BYTES)         // 40960
#define SM_W0V  (SM_A0 + A0_BYTES)         // 53248 (27*128*4 = 13824)
#define SM_W2   (SM_W0V + 13824)           // 67072 (1536)
#define SM_H0   (SM_W2 + 1536)             // 68608 (512)
#define SM_BB1  (SM_H0 + 512)              // 69120 (512)
#define SM_WGT  (SM_BB1 + 512)             // 69632 (1024)
#define SM_VB   (SM_WGT + 1024)            // 70656 (128)
#define SM_WS   (SM_VB + 128)              // 70784 (64)
#define SM_RED  (SM_WS + 64)               // 70848 (96)
#define SMEM_BYTES 71040

__device__ __align__(16) unsigned char g_B1[B1_BYTES];  // W1^T fp16 [n][k], stride 272
__device__ __align__(16) unsigned char g_B0[B0_BYTES];  // W0feat^T fp16 [n][k16], stride 48

__global__ void prep_kernel(const float* __restrict__ W1, const float* __restrict__ W0) {
    int idx = blockIdx.x * blockDim.x + threadIdx.x;   // 16384
    {
        int n = idx >> 7, k = idx & 127;
        *(__half*)(g_B1 + n * ASTRIDE1 + k * 2) = __float2half_rn(W1[k * WIDTH + n]);
    }
    if (idx < 2048) {
        int n = idx >> 4, k = idx & 15;
        float v = (k < K0D) ? W0[k * WIDTH + n] : 0.0f;
        *(__half*)(g_B0 + n * ASTRIDE0 + k * 2) = __float2half_rn(v);
    }
}

__device__ __forceinline__ void ldsm4(uint32_t* r, uint32_t addr) {
    asm volatile("ldmatrix.sync.aligned.m8n8.x4.shared.b16 {%0,%1,%2,%3}, [%4];"
        : "=r"(r[0]), "=r"(r[1]), "=r"(r[2]), "=r"(r[3]) : "r"(addr));
}

__device__ __forceinline__ void mma_fp16(float* c, const uint32_t* a, const uint32_t* b) {
    asm volatile(
        "mma.sync.aligned.m16n8k16.row.col.f32.f16.f16.f32 "
        "{%0,%1,%2,%3}, {%4,%5,%6,%7}, {%8,%9}, {%0,%1,%2,%3};"
        : "+f"(c[0]), "+f"(c[1]), "+f"(c[2]), "+f"(c[3])
        : "r"(a[0]), "r"(a[1]), "r"(a[2]), "r"(a[3]), "r"(b[0]), "r"(b[1]));
}

__device__ __forceinline__ uint32_t packh2(float a, float b) {
    __half2 h = __floats2half2_rn(a, b);
    return *(uint32_t*)&h;
}

__global__ __launch_bounds__(256, 2)
void dvgo_pers_kernel(const float* __restrict__ ro, const float* __restrict__ rd,
                      const float* __restrict__ density, const float* __restrict__ k0,
                      const float* __restrict__ W0, const float* __restrict__ b0,
                      const float* __restrict__ b1,
                      const float* __restrict__ W2, const float* __restrict__ b2,
                      float* __restrict__ out, int nrays)
{
    extern __shared__ __align__(16) char smem[];
    const uint32_t sbs = (uint32_t)__cvta_generic_to_shared(smem);
    const int tid = threadIdx.x;
    const int wid = tid >> 5;
    const int lane = tid & 31;

    // ================= one-time weight staging =================
    {
        const uint4* src = (const uint4*)g_B1;
        uint4* dst = (uint4*)(smem + SM_B1);
        #pragma unroll
        for (int i = 0; i < 8; ++i) dst[tid + 256 * i] = src[tid + 256 * i];
        if (tid < 128) dst[2048 + tid] = src[2048 + tid];
    }
    {
        const uint4* src = (const uint4*)g_B0;
        uint4* dst = (uint4*)(smem + SM_B0);
        dst[tid] = src[tid];
        if (tid < 128) dst[256 + tid] = src[256 + tid];
    }
    {   // W0 view rows 12..38 (3456 floats)
        float* s = (float*)(smem + SM_W0V);
        const float* g = W0 + 12 * WIDTH;
        for (int i = tid; i < 27 * WIDTH; i += 256) s[i] = g[i];
    }
    if (tid < 96) ((float4*)(smem + SM_W2))[tid] = ((const float4*)W2)[tid];
    float* sb1 = (float*)(smem + SM_BB1);
    if (tid < 128) sb1[tid] = b1[tid];
    const float b20 = __ldg(b2), b21 = __ldg(b2+1), b22 = __ldg(b2+2);

    float* svb  = (float*)(smem + SM_VB);
    float* sWs  = (float*)(smem + SM_WS);
    float* sWgt = (float*)(smem + SM_WGT);
    float* sh0  = (float*)(smem + SM_H0);
    float* red  = (float*)(smem + SM_RED);
    const float* sW0v = (const float*)(smem + SM_W0V);
    const float* sW2  = (const float*)(smem + SM_W2);

    // frag base addresses (loop-invariant)
    const uint32_t aAddr0 = sbs + SM_A0
        + (uint32_t)(wid*32 + (lane & 15)) * ASTRIDE0 + (uint32_t)((lane >> 4) * 16);
    const uint32_t bAddr0 = sbs + SM_B0
        + (uint32_t)((lane & 7) + ((lane >> 4) & 1) * 8) * ASTRIDE0
        + (uint32_t)(((lane >> 3) & 1) * 16);
    const uint32_t bAddr1 = sbs + SM_B1
        + (uint32_t)((lane & 7) + ((lane >> 4) & 1) * 8) * ASTRIDE1
        + (uint32_t)(((lane >> 3) & 1) * 16);

    // ================= ray loop =================
    for (int ray = blockIdx.x; ray < nrays; ray += NBLOCKS) {

        const float ox = ro[3*ray+0], oy = ro[3*ray+1], oz = ro[3*ray+2];
        const float dx = rd[3*ray+0], dy = rd[3*ray+1], dz = rd[3*ray+2];

        if (tid == 0) {
            float inv = 1.0f / sqrtf(dx*dx + dy*dy + dz*dz);
            float v[3] = {dx*inv, dy*inv, dz*inv};
            svb[0] = v[0]; svb[1] = v[1]; svb[2] = v[2];
            #pragma unroll
            for (int i = 0; i < 3; ++i)
                #pragma unroll
                for (int j = 0; j < 4; ++j) {
                    float a = v[i] * (float)(1 << j);
                    svb[3  + i*4 + j] = sinf(a);
                    svb[15 + i*4 + j] = cosf(a);
                }
        }

        // ---- sample point + trilinear setup ----
        const float tpar = NEAR_T + (FAR_T - NEAR_T) * ((float)tid * (1.0f/(float)(NS-1)));
        float gx = (ox + dx*tpar + 1.0f) * (0.5f * 159.0f);
        float gy = (oy + dy*tpar + 1.0f) * (0.5f * 159.0f);
        float gz = (oz + dz*tpar + 1.0f) * (0.5f * 159.0f);
        gx = fminf(fmaxf(gx, 0.0f), 159.0f);
        gy = fminf(fmaxf(gy, 0.0f), 159.0f);
        gz = fminf(fmaxf(gz, 0.0f), 159.0f);
        int x0 = min((int)floorf(gx), 158);
        int y0 = min((int)floorf(gy), 158);
        int z0 = min((int)floorf(gz), 158);
        const float fx = gx - (float)x0, fy = gy - (float)y0, fz = gz - (float)z0;
        const int idx000 = (x0*GRIDN + y0)*GRIDN + z0;
        const float wx0 = 1.0f-fx, wy0 = 1.0f-fy, wz0 = 1.0f-fz;
        float w8[8];
        w8[0]=wx0*wy0*wz0; w8[1]=wx0*wy0*fz; w8[2]=wx0*fy*wz0; w8[3]=wx0*fy*fz;
        w8[4]=fx*wy0*wz0;  w8[5]=fx*wy0*fz;  w8[6]=fx*fy*wz0;  w8[7]=fx*fy*fz;
        const int offs[8] = {0, 1, GRIDN, GRIDN+1,
                             GRIDN*GRIDN, GRIDN*GRIDN+1, GRIDN*GRIDN+GRIDN, GRIDN*GRIDN+GRIDN+1};

        // ---- density -> alpha ----
        float sigma = 0.0f;
        {
            const float* g = density + idx000;
            #pragma unroll
            for (int c = 0; c < 8; ++c) sigma += w8[c] * __ldg(g + offs[c]);
        }
        const float e = expf(sigma + ACT_SHIFT);
        const float oneminus = 1.0f / sqrtf(1.0f + e);
        const float alpha = 1.0f - oneminus;

        // ---- k0 gather (12 ch) -> A0 row (fp16, k pad 16) — warp-local rows ----
        {
            float feat[K0D];
            #pragma unroll
            for (int c = 0; c < K0D; ++c) {
                const float* g = k0 + (size_t)c * (GRIDN*GRIDN*GRIDN) + idx000;
                float acc = 0.0f;
                #pragma unroll
                for (int cn = 0; cn < 8; ++cn) acc += w8[cn] * __ldg(g + offs[cn]);
                feat[c] = acc;
            }
            uint32_t pk[8];
            #pragma unroll
            for (int q = 0; q < 6; ++q) pk[q] = packh2(feat[2*q], feat[2*q+1]);
            pk[6] = 0u; pk[7] = 0u;
            char* arow = smem + SM_A0 + tid * ASTRIDE0;
            *(uint4*)(arow)      = make_uint4(pk[0], pk[1], pk[2], pk[3]);
            *(uint4*)(arow + 16) = make_uint4(pk[4], pk[5], pk[6], pk[7]);
        }

        // ---- cumprod scan: shfl warp scan + cross-warp ----
        float val = oneminus + 1e-10f;
        #pragma unroll
        for (int d = 1; d < 32; d <<= 1) {
            float p = __shfl_up_sync(0xFFFFFFFF, val, d);
            if (lane >= d) val *= p;
        }
        if (lane == 31) sWs[wid] = val;
        __syncthreads();                       // [1] also fences weight staging on iter 0
        if (tid < 8) {
            float w = sWs[tid];
            #pragma unroll
            for (int d = 1; d < 8; d <<= 1) {
                float p = __shfl_up_sync(0xFF, w, d);
                if (tid >= d) w *= p;
            }
            sWs[8 + tid] = w;
        }
        __syncthreads();                       // [2]
        const float pref = (wid == 0) ? 1.0f : sWs[8 + wid - 1];
        const float ainv = sWs[15];
        float Texc;
        {
            float incl = pref * val;
            float p = __shfl_up_sync(0xFFFFFFFF, incl, 1);
            Texc = (lane == 0) ? pref : p;
        }
        sWgt[tid] = alpha * Texc;              // warp-local consumption

        // ---- per-ray folded layer0 bias ----
        if (tid < 128) {
            float acc = b0[tid];
            #pragma unroll
            for (int dd = 0; dd < 27; ++dd)
                acc += svb[dd] * sW0v[dd*WIDTH + tid];
            sh0[tid] = acc;
        }
        __syncthreads();                       // [3] sh0 + A0 visible

        // ---- GEMM0 (two n-halves) -> A-fragments in registers ----
        uint32_t afrag[2][8][4];
        {
            uint32_t a0_[4], a1_[4];
            ldsm4(a0_, aAddr0);
            ldsm4(a1_, aAddr0 + 16u * ASTRIDE0);
            #pragma unroll
            for (int nh = 0; nh < 2; ++nh) {
                float acc0[2][8][4];
                #pragma unroll
                for (int mt = 0; mt < 2; ++mt)
                    #pragma unroll
                    for (int nt = 0; nt < 8; ++nt)
                        #pragma unroll
                        for (int q = 0; q < 4; ++q) acc0[mt][nt][q] = 0.0f;
                #pragma unroll
                for (int nt2 = 0; nt2 < 4; ++nt2) {
                    uint32_t b[4];
                    ldsm4(b, bAddr0 + (uint32_t)(nh*4 + nt2) * (16u * ASTRIDE0));
                    mma_fp16(acc0[0][2*nt2],     a0_, b);
                    mma_fp16(acc0[0][2*nt2 + 1], a0_, b + 2);
                    mma_fp16(acc0[1][2*nt2],     a1_, b);
                    mma_fp16(acc0[1][2*nt2 + 1], a1_, b + 2);
                }
                // convert: acc pair (2j2, 2j2+1) -> A-frag of k-block nh*4+j2
                #pragma unroll
                for (int j2 = 0; j2 < 4; ++j2) {
                    const int c0 = (nh*8 + 2*j2)*8 + 2*(lane & 3);
                    const float2 hbA = *(const float2*)(sh0 + c0);
                    const float2 hbB = *(const float2*)(sh0 + c0 + 8);
                    #pragma unroll
                    for (int mt = 0; mt < 2; ++mt) {
                        afrag[mt][nh*4+j2][0] = packh2(fmaxf(acc0[mt][2*j2][0] + hbA.x, 0.0f),
                                                       fmaxf(acc0[mt][2*j2][1] + hbA.y, 0.0f));
                        afrag[mt][nh*4+j2][1] = packh2(fmaxf(acc0[mt][2*j2][2] + hbA.x, 0.0f),
                                                       fmaxf(acc0[mt][2*j2][3] + hbA.y, 0.0f));
                        afrag[mt][nh*4+j2][2] = packh2(fmaxf(acc0[mt][2*j2+1][0] + hbB.x, 0.0f),
                                                       fmaxf(acc0[mt][2*j2+1][1] + hbB.y, 0.0f));
                        afrag[mt][nh*4+j2][3] = packh2(fmaxf(acc0[mt][2*j2+1][2] + hbB.x, 0.0f),
                                                       fmaxf(acc0[mt][2*j2+1][3] + hbB.y, 0.0f));
                    }
                }
            }
        }

        // ---- GEMM1 (two n-halves) + epilogue1 ----
        float rsum[2][2][3];
        #pragma unroll
        for (int mt = 0; mt < 2; ++mt)
            #pragma unroll
            for (int rh = 0; rh < 2; ++rh)
                #pragma unroll
                for (int c = 0; c < 3; ++c) rsum[mt][rh][c] = 0.0f;

        #pragma unroll 1
        for (int nh = 0; nh < 2; ++nh) {
            float acc[2][8][4];
            #pragma unroll
            for (int mt = 0; mt < 2; ++mt)
                #pragma unroll
                for (int nt = 0; nt < 8; ++nt)
                    #pragma unroll
                    for (int q = 0; q < 4; ++q) acc[mt][nt][q] = 0.0f;
            #pragma unroll
            for (int k = 0; k < 8; ++k) {
                #pragma unroll
                for (int nt2 = 0; nt2 < 4; ++nt2) {
                    uint32_t b[4];
                    ldsm4(b, bAddr1 + (uint32_t)(k*32)
                             + (uint32_t)(nh*4 + nt2) * (16u * ASTRIDE1));
                    mma_fp16(acc[0][2*nt2],     afrag[0][k], b);
                    mma_fp16(acc[0][2*nt2 + 1], afrag[0][k], b + 2);
                    mma_fp16(acc[1][2*nt2],     afrag[1][k], b);
                    mma_fp16(acc[1][2*nt2 + 1], afrag[1][k], b + 2);
                }
            }
            #pragma unroll
            for (int mt = 0; mt < 2; ++mt)
                #pragma unroll
                for (int nt = 0; nt < 8; ++nt) {
                    const int c0 = (nh*8 + nt)*8 + 2*(lane & 3);
                    const float bA = sb1[c0], bB = sb1[c0+1];
                    const float h00 = fmaxf(acc[mt][nt][0] + bA, 0.0f);
                    const float h01 = fmaxf(acc[mt][nt][1] + bB, 0.0f);
                    const float h10 = fmaxf(acc[mt][nt][2] + bA, 0.0f);
                    const float h11 = fmaxf(acc[mt][nt][3] + bB, 0.0f);
                    #pragma unroll
                    for (int c = 0; c < 3; ++c) {
                        const float wA = sW2[c0*3 + c], wB = sW2[c0*3 + 3 + c];
                        rsum[mt][0][c] += h00*wA + h01*wB;
                        rsum[mt][1][c] += h10*wA + h11*wB;
                    }
                }
        }

        #pragma unroll
        for (int mt = 0; mt < 2; ++mt)
            #pragma unroll
            for (int rh = 0; rh < 2; ++rh)
                #pragma unroll
                for (int c = 0; c < 3; ++c) {
                    float v = rsum[mt][rh][c];
                    v += __shfl_xor_sync(0xFFFFFFFF, v, 1);
                    v += __shfl_xor_sync(0xFFFFFFFF, v, 2);
                    rsum[mt][rh][c] = v;
                }

        float pr = 0.0f, pg = 0.0f, pb = 0.0f;
        if ((lane & 3) == 0) {
            #pragma unroll
            for (int mt = 0; mt < 2; ++mt)
                #pragma unroll
                for (int rh = 0; rh < 2; ++rh) {
                    const int s = wid*32 + mt*16 + rh*8 + (lane >> 2);
                    const float w = sWgt[s];
                    pr += w * (1.0f/(1.0f + expf(-(rsum[mt][rh][0] + b20))));
                    pg += w * (1.0f/(1.0f + expf(-(rsum[mt][rh][1] + b21))));
                    pb += w * (1.0f/(1.0f + expf(-(rsum[mt][rh][2] + b22))));
                }
        }
        #pragma unroll
        for (int d = 4; d < 32; d <<= 1) {
            pr += __shfl_xor_sync(0xFFFFFFFF, pr, d);
            pg += __shfl_xor_sync(0xFFFFFFFF, pg, d);
            pb += __shfl_xor_sync(0xFFFFFFFF, pb, d);
        }
        if (lane == 0) {
            red[wid*3 + 0] = pr;
            red[wid*3 + 1] = pg;
            red[wid*3 + 2] = pb;
        }
        __syncthreads();                       // [4] end-of-iter: red + smem reuse fence
        if (tid == 0) {
            float r = ainv, g = ainv, b = ainv;
            #pragma unroll
            for (int w = 0; w < 8; ++w) {
                r += red[w*3 + 0];
                g += red[w*3 + 1];
                b += red[w*3 + 2];
            }
            out[3*ray + 0] = r;
            out[3*ray + 1] = g;
            out[3*ray + 2] = b;
        }
    }
}

extern "C" void kernel_launch(void* const* d_in, const int* in_sizes, int n_in,
                              void* d_out, int out_size) {
    const float* ro      = (const float*)d_in[0];
    const float* rd      = (const float*)d_in[1];
    const float* density = (const float*)d_in[2];
    const float* k0      = (const float*)d_in[3];
    const float* W0      = (const float*)d_in[4];
    const float* b0      = (const float*)d_in[5];
    const float* W1      = (const float*)d_in[6];
    const float* b1      = (const float*)d_in[7];
    const float* W2      = (const float*)d_in[8];
    const float* b2      = (const float*)d_in[9];
    float* out = (float*)d_out;

    const int nrays = in_sizes[0] / 3;

    prep_kernel<<<64, 256>>>(W1, W0);

    cudaFuncSetAttribute(dvgo_pers_kernel,
                         cudaFuncAttributeMaxDynamicSharedMemorySize, SMEM_BYTES);
    dvgo_pers_kernel<<<NBLOCKS, 256, SMEM_BYTES>>>(ro, rd, density, k0,
                                                   W0, b0, b1, W2, b2, out, nrays);
}

// round 15
// speedup vs baseline: 7.1543x; 1.1621x over previous
#include <cuda_runtime.h>
#include <cuda_fp16.h>
#include <cstdint>

#define GRIDN 160
#define NS 256
#define WIDTH 128
#define K0D 12
#define NEAR_T 0.2f
#define FAR_T 1.8f
#define ACT_SHIFT -4.59511985013459f
#define NBLOCKS 296

// row strides conflict-free for ldmatrix: words%32 == 4 (272B) / 12 (48B)
#define ASTRIDE1 272
#define ASTRIDE0 48
#define B1_BYTES (128 * ASTRIDE1)   // 34816
#define B2_BYTES (8 * ASTRIDE1)     // 2176
#define A0_BYTES (256 * ASTRIDE0)   // 12288
#define B0_BYTES (128 * ASTRIDE0)   // 6144

// smem byte offsets
#define SM_B1   0
#define SM_B0   34816
#define SM_B2   40960
#define SM_A0   43136
#define SM_W0V  55424            // 27*128*4 = 13824
#define SM_H0   69248            // 512
#define SM_BB1  69760            // 512
#define SM_WGT  70272            // 1024
#define SM_VB   71296            // 128
#define SM_WS   71424            // 64
#define SM_RED  71488            // 96
#define SMEM_BYTES 71680

__device__ __align__(16) unsigned char g_B1[B1_BYTES];  // W1^T fp16 [n][k], stride 272
__device__ __align__(16) unsigned char g_B0[B0_BYTES];  // W0feat^T fp16 [n][k16], stride 48
__device__ __align__(16) unsigned char g_B2[B2_BYTES];  // W2hat fp16 [n8][k128], stride 272

__global__ void prep_kernel(const float* __restrict__ W1, const float* __restrict__ W0,
                            const float* __restrict__ W2) {
    int idx = blockIdx.x * blockDim.x + threadIdx.x;   // 16384
    {
        int n = idx >> 7, k = idx & 127;
        *(__half*)(g_B1 + n * ASTRIDE1 + k * 2) = __float2half_rn(W1[k * WIDTH + n]);
    }
    if (idx < 2048) {
        int n = idx >> 4, k = idx & 15;
        float v = (k < K0D) ? W0[k * WIDTH + n] : 0.0f;
        *(__half*)(g_B0 + n * ASTRIDE0 + k * 2) = __float2half_rn(v);
    }
    if (idx < 1024) {
        int n = idx >> 7, k = idx & 127;
        float v = (n < 3) ? W2[k * 3 + n] : 0.0f;
        *(__half*)(g_B2 + n * ASTRIDE1 + k * 2) = __float2half_rn(v);
    }
}

__device__ __forceinline__ void ldsm4(uint32_t* r, uint32_t addr) {
    asm volatile("ldmatrix.sync.aligned.m8n8.x4.shared.b16 {%0,%1,%2,%3}, [%4];"
        : "=r"(r[0]), "=r"(r[1]), "=r"(r[2]), "=r"(r[3]) : "r"(addr));
}

__device__ __forceinline__ void mma_fp16(float* c, const uint32_t* a, const uint32_t* b) {
    asm volatile(
        "mma.sync.aligned.m16n8k16.row.col.f32.f16.f16.f32 "
        "{%0,%1,%2,%3}, {%4,%5,%6,%7}, {%8,%9}, {%0,%1,%2,%3};"
        : "+f"(c[0]), "+f"(c[1]), "+f"(c[2]), "+f"(c[3])
        : "r"(a[0]), "r"(a[1]), "r"(a[2]), "r"(a[3]), "r"(b[0]), "r"(b[1]));
}

__device__ __forceinline__ uint32_t packh2(float a, float b) {
    __half2 h = __floats2half2_rn(a, b);
    return *(uint32_t*)&h;
}

__global__ __launch_bounds__(256, 2)
void dvgo_pers_kernel(const float* __restrict__ ro, const float* __restrict__ rd,
                      const float* __restrict__ density, const float* __restrict__ k0,
                      const float* __restrict__ W0, const float* __restrict__ b0,
                      const float* __restrict__ b1, const float* __restrict__ b2,
                      float* __restrict__ out, int nrays)
{
    extern __shared__ __align__(16) char smem[];
    const uint32_t sbs = (uint32_t)__cvta_generic_to_shared(smem);
    const int tid = threadIdx.x;
    const int wid = tid >> 5;
    const int lane = tid & 31;

    // ================= one-time weight staging =================
    {
        const uint4* src = (const uint4*)g_B1;
        uint4* dst = (uint4*)(smem + SM_B1);
        #pragma unroll
        for (int i = 0; i < 8; ++i) dst[tid + 256 * i] = src[tid + 256 * i];
        if (tid < 128) dst[2048 + tid] = src[2048 + tid];
    }
    {
        const uint4* src = (const uint4*)g_B0;
        uint4* dst = (uint4*)(smem + SM_B0);
        dst[tid] = src[tid];
        if (tid < 128) dst[256 + tid] = src[256 + tid];
    }
    if (tid < 136) ((uint4*)(smem + SM_B2))[tid] = ((const uint4*)g_B2)[tid];
    {   // W0 view rows 12..38 (3456 floats)
        float* s = (float*)(smem + SM_W0V);
        const float* g = W0 + 12 * WIDTH;
        for (int i = tid; i < 27 * WIDTH; i += 256) s[i] = g[i];
    }
    float* sb1 = (float*)(smem + SM_BB1);
    if (tid < 128) sb1[tid] = b1[tid];
    const float b20 = __ldg(b2), b21 = __ldg(b2+1), b22 = __ldg(b2+2);

    float* svb  = (float*)(smem + SM_VB);
    float* sWs  = (float*)(smem + SM_WS);
    float* sWgt = (float*)(smem + SM_WGT);
    float* sh0  = (float*)(smem + SM_H0);
    float* red  = (float*)(smem + SM_RED);
    const float* sW0v = (const float*)(smem + SM_W0V);

    // frag base addresses (loop-invariant)
    const uint32_t aAddr0 = sbs + SM_A0
        + (uint32_t)(wid*32 + (lane & 15)) * ASTRIDE0 + (uint32_t)((lane >> 4) * 16);
    const uint32_t bAddr0 = sbs + SM_B0
        + (uint32_t)((lane & 7) + ((lane >> 4) & 1) * 8) * ASTRIDE0
        + (uint32_t)(((lane >> 3) & 1) * 16);
    const uint32_t bAddr1 = sbs + SM_B1
        + (uint32_t)((lane & 7) + ((lane >> 4) & 1) * 8) * ASTRIDE1
        + (uint32_t)(((lane >> 3) & 1) * 16);
    const uint32_t bAddr2 = sbs + SM_B2
        + (uint32_t)(lane & 7) * ASTRIDE1 + (uint32_t)((lane >> 3) * 16);

    // ================= ray loop =================
    for (int ray = blockIdx.x; ray < nrays; ray += NBLOCKS) {

        const float ox = ro[3*ray+0], oy = ro[3*ray+1], oz = ro[3*ray+2];
        const float dx = rd[3*ray+0], dy = rd[3*ray+1], dz = rd[3*ray+2];

        if (tid == 0) {
            float inv = 1.0f / sqrtf(dx*dx + dy*dy + dz*dz);
            float v[3] = {dx*inv, dy*inv, dz*inv};
            svb[0] = v[0]; svb[1] = v[1]; svb[2] = v[2];
            #pragma unroll
            for (int i = 0; i < 3; ++i)
                #pragma unroll
                for (int j = 0; j < 4; ++j) {
                    float a = v[i] * (float)(1 << j);
                    svb[3  + i*4 + j] = sinf(a);
                    svb[15 + i*4 + j] = cosf(a);
                }
        }

        // ---- sample point + trilinear setup ----
        const float tpar = NEAR_T + (FAR_T - NEAR_T) * ((float)tid * (1.0f/(float)(NS-1)));
        float gx = (ox + dx*tpar + 1.0f) * (0.5f * 159.0f);
        float gy = (oy + dy*tpar + 1.0f) * (0.5f * 159.0f);
        float gz = (oz + dz*tpar + 1.0f) * (0.5f * 159.0f);
        gx = fminf(fmaxf(gx, 0.0f), 159.0f);
        gy = fminf(fmaxf(gy, 0.0f), 159.0f);
        gz = fminf(fmaxf(gz, 0.0f), 159.0f);
        int x0 = min((int)floorf(gx), 158);
        int y0 = min((int)floorf(gy), 158);
        int z0 = min((int)floorf(gz), 158);
        const float fx = gx - (float)x0, fy = gy - (float)y0, fz = gz - (float)z0;
        const int idx000 = (x0*GRIDN + y0)*GRIDN + z0;
        const float wx0 = 1.0f-fx, wy0 = 1.0f-fy, wz0 = 1.0f-fz;
        float w8[8];
        w8[0]=wx0*wy0*wz0; w8[1]=wx0*wy0*fz; w8[2]=wx0*fy*wz0; w8[3]=wx0*fy*fz;
        w8[4]=fx*wy0*wz0;  w8[5]=fx*wy0*fz;  w8[6]=fx*fy*wz0;  w8[7]=fx*fy*fz;
        const int offs[8] = {0, 1, GRIDN, GRIDN+1,
                             GRIDN*GRIDN, GRIDN*GRIDN+1, GRIDN*GRIDN+GRIDN, GRIDN*GRIDN+GRIDN+1};

        // ---- density -> alpha ----
        float sigma = 0.0f;
        {
            const float* g = density + idx000;
            #pragma unroll
            for (int c = 0; c < 8; ++c) sigma += w8[c] * __ldg(g + offs[c]);
        }
        const float e = expf(sigma + ACT_SHIFT);
        const float oneminus = 1.0f / sqrtf(1.0f + e);
        const float alpha = 1.0f - oneminus;

        // ---- k0 gather (12 ch) -> A0 row (fp16, k pad 16) ----
        {
            float feat[K0D];
            #pragma unroll
            for (int c = 0; c < K0D; ++c) {
                const float* g = k0 + (size_t)c * (GRIDN*GRIDN*GRIDN) + idx000;
                float acc = 0.0f;
                #pragma unroll
                for (int cn = 0; cn < 8; ++cn) acc += w8[cn] * __ldg(g + offs[cn]);
                feat[c] = acc;
            }
            uint32_t pk[8];
            #pragma unroll
            for (int q = 0; q < 6; ++q) pk[q] = packh2(feat[2*q], feat[2*q+1]);
            pk[6] = 0u; pk[7] = 0u;
            char* arow = smem + SM_A0 + tid * ASTRIDE0;
            *(uint4*)(arow)      = make_uint4(pk[0], pk[1], pk[2], pk[3]);
            *(uint4*)(arow + 16) = make_uint4(pk[4], pk[5], pk[6], pk[7]);
        }

        // ---- cumprod scan: shfl warp scan + cross-warp ----
        float val = oneminus + 1e-10f;
        #pragma unroll
        for (int d = 1; d < 32; d <<= 1) {
            float p = __shfl_up_sync(0xFFFFFFFF, val, d);
            if (lane >= d) val *= p;
        }
        if (lane == 31) sWs[wid] = val;
        __syncthreads();                       // [1] also fences weight staging (iter 0)
        if (tid < 8) {
            float w = sWs[tid];
            #pragma unroll
            for (int d = 1; d < 8; d <<= 1) {
                float p = __shfl_up_sync(0xFF, w, d);
                if (tid >= d) w *= p;
            }
            sWs[8 + tid] = w;
        }
        __syncthreads();                       // [2]
        const float pref = (wid == 0) ? 1.0f : sWs[8 + wid - 1];
        const float ainv = sWs[15];
        float Texc;
        {
            float incl = pref * val;
            float p = __shfl_up_sync(0xFFFFFFFF, incl, 1);
            Texc = (lane == 0) ? pref : p;
        }
        sWgt[tid] = alpha * Texc;

        // ---- per-ray folded layer0 bias ----
        if (tid < 128) {
            float acc = b0[tid];
            #pragma unroll
            for (int dd = 0; dd < 27; ++dd)
                acc += svb[dd] * sW0v[dd*WIDTH + tid];
            sh0[tid] = acc;
        }
        __syncthreads();                       // [3] sh0 + A0 visible

        // ---- GEMM0 (two n-halves) -> A-fragments in registers ----
        uint32_t afrag[2][8][4];
        {
            uint32_t a0_[4], a1_[4];
            ldsm4(a0_, aAddr0);
            ldsm4(a1_, aAddr0 + 16u * ASTRIDE0);
            #pragma unroll
            for (int nh = 0; nh < 2; ++nh) {
                float acc0[2][8][4];
                #pragma unroll
                for (int mt = 0; mt < 2; ++mt)
                    #pragma unroll
                    for (int nt = 0; nt < 8; ++nt)
                        #pragma unroll
                        for (int q = 0; q < 4; ++q) acc0[mt][nt][q] = 0.0f;
                #pragma unroll
                for (int nt2 = 0; nt2 < 4; ++nt2) {
                    uint32_t b[4];
                    ldsm4(b, bAddr0 + (uint32_t)(nh*4 + nt2) * (16u * ASTRIDE0));
                    mma_fp16(acc0[0][2*nt2],     a0_, b);
                    mma_fp16(acc0[0][2*nt2 + 1], a0_, b + 2);
                    mma_fp16(acc0[1][2*nt2],     a1_, b);
                    mma_fp16(acc0[1][2*nt2 + 1], a1_, b + 2);
                }
                #pragma unroll
                for (int j2 = 0; j2 < 4; ++j2) {
                    const int c0 = (nh*8 + 2*j2)*8 + 2*(lane & 3);
                    const float2 hbA = *(const float2*)(sh0 + c0);
                    const float2 hbB = *(const float2*)(sh0 + c0 + 8);
                    #pragma unroll
                    for (int mt = 0; mt < 2; ++mt) {
                        afrag[mt][nh*4+j2][0] = packh2(fmaxf(acc0[mt][2*j2][0] + hbA.x, 0.0f),
                                                       fmaxf(acc0[mt][2*j2][1] + hbA.y, 0.0f));
                        afrag[mt][nh*4+j2][1] = packh2(fmaxf(acc0[mt][2*j2][2] + hbA.x, 0.0f),
                                                       fmaxf(acc0[mt][2*j2][3] + hbA.y, 0.0f));
                        afrag[mt][nh*4+j2][2] = packh2(fmaxf(acc0[mt][2*j2+1][0] + hbB.x, 0.0f),
                                                       fmaxf(acc0[mt][2*j2+1][1] + hbB.y, 0.0f));
                        afrag[mt][nh*4+j2][3] = packh2(fmaxf(acc0[mt][2*j2+1][2] + hbB.x, 0.0f),
                                                       fmaxf(acc0[mt][2*j2+1][3] + hbB.y, 0.0f));
                    }
                }
            }
        }

        // ---- GEMM1 (two n-halves) + fragment-relayout + GEMM2 (rgb) ----
        float acc2[2][4];
        #pragma unroll
        for (int mt = 0; mt < 2; ++mt)
            #pragma unroll
            for (int q = 0; q < 4; ++q) acc2[mt][q] = 0.0f;

        #pragma unroll 1
        for (int nh = 0; nh < 2; ++nh) {
            float acc[2][8][4];
            #pragma unroll
            for (int mt = 0; mt < 2; ++mt)
                #pragma unroll
                for (int nt = 0; nt < 8; ++nt)
                    #pragma unroll
                    for (int q = 0; q < 4; ++q) acc[mt][nt][q] = 0.0f;
            #pragma unroll
            for (int k = 0; k < 8; ++k) {
                #pragma unroll
                for (int nt2 = 0; nt2 < 4; ++nt2) {
                    uint32_t b[4];
                    ldsm4(b, bAddr1 + (uint32_t)(k*32)
                             + (uint32_t)(nh*4 + nt2) * (16u * ASTRIDE1));
                    mma_fp16(acc[0][2*nt2],     afrag[0][k], b);
                    mma_fp16(acc[0][2*nt2 + 1], afrag[0][k], b + 2);
                    mma_fp16(acc[1][2*nt2],     afrag[1][k], b);
                    mma_fp16(acc[1][2*nt2 + 1], afrag[1][k], b + 2);
                }
            }
            // relayout: layer1 acc (+b1, relu) -> GEMM2 A-frags; accumulate rgb
            uint32_t b2f[8];
            ldsm4(b2f,     bAddr2 + (uint32_t)(nh*128));
            ldsm4(b2f + 4, bAddr2 + (uint32_t)(nh*128 + 64));
            #pragma unroll
            for (int j = 0; j < 4; ++j) {
                const int c0 = nh*64 + 16*j + 2*(lane & 3);
                const float2 bA = *(const float2*)(sb1 + c0);
                const float2 bB = *(const float2*)(sb1 + c0 + 8);
                #pragma unroll
                for (int mt = 0; mt < 2; ++mt) {
                    uint32_t hf[4];
                    hf[0] = packh2(fmaxf(acc[mt][2*j][0] + bA.x, 0.0f),
                                   fmaxf(acc[mt][2*j][1] + bA.y, 0.0f));
                    hf[1] = packh2(fmaxf(acc[mt][2*j][2] + bA.x, 0.0f),
                                   fmaxf(acc[mt][2*j][3] + bA.y, 0.0f));
                    hf[2] = packh2(fmaxf(acc[mt][2*j+1][0] + bB.x, 0.0f),
                                   fmaxf(acc[mt][2*j+1][1] + bB.y, 0.0f));
                    hf[3] = packh2(fmaxf(acc[mt][2*j+1][2] + bB.x, 0.0f),
                                   fmaxf(acc[mt][2*j+1][3] + bB.y, 0.0f));
                    mma_fp16(acc2[mt], hf, b2f + 2*j);
                }
            }
        }

        // ---- extract rgb: cols 0,1 in lanes %4==0; col 2 in lanes %4==1 ----
        float pr = 0.0f, pg = 0.0f, pb = 0.0f;
        #pragma unroll
        for (int mt = 0; mt < 2; ++mt) {
            const int r0 = wid*32 + mt*16 + (lane >> 2);
            const float w0 = sWgt[r0], w1 = sWgt[r0 + 8];
            if ((lane & 3) == 0) {
                pr += w0 * (1.0f/(1.0f + expf(-(acc2[mt][0] + b20))))
                    + w1 * (1.0f/(1.0f + expf(-(acc2[mt][2] + b20))));
                pg += w0 * (1.0f/(1.0f + expf(-(acc2[mt][1] + b21))))
                    + w1 * (1.0f/(1.0f + expf(-(acc2[mt][3] + b21))));
            } else if ((lane & 3) == 1) {
                pb += w0 * (1.0f/(1.0f + expf(-(acc2[mt][0] + b22))))
                    + w1 * (1.0f/(1.0f + expf(-(acc2[mt][2] + b22))));
            }
        }
        #pragma unroll
        for (int d = 1; d < 32; d <<= 1) {
            pr += __shfl_xor_sync(0xFFFFFFFF, pr, d);
            pg += __shfl_xor_sync(0xFFFFFFFF, pg, d);
            pb += __shfl_xor_sync(0xFFFFFFFF, pb, d);
        }
        if (lane == 0) {
            red[wid*3 + 0] = pr;
            red[wid*3 + 1] = pg;
            red[wid*3 + 2] = pb;
        }
        __syncthreads();                       // [4] red ready + smem reuse fence
        if (tid == 0) {
            float r = ainv, g = ainv, b = ainv;
            #pragma unroll
            for (int w = 0; w < 8; ++w) {
                r += red[w*3 + 0];
                g += red[w*3 + 1];
                b += red[w*3 + 2];
            }
            out[3*ray + 0] = r;
            out[3*ray + 1] = g;
            out[3*ray + 2] = b;
        }
    }
}

extern "C" void kernel_launch(void* const* d_in, const int* in_sizes, int n_in,
                              void* d_out, int out_size) {
    const float* ro      = (const float*)d_in[0];
    const float* rd      = (const float*)d_in[1];
    const float* density = (const float*)d_in[2];
    const float* k0      = (const float*)d_in[3];
    const float* W0      = (const float*)d_in[4];
    const float* b0      = (const float*)d_in[5];
    const float* W1      = (const float*)d_in[6];
    const float* b1      = (const float*)d_in[7];
    const float* W2      = (const float*)d_in[8];
    const float* b2      = (const float*)d_in[9];
    float* out = (float*)d_out;

    const int nrays = in_sizes[0] / 3;

    prep_kernel<<<64, 256>>>(W1, W0, W2);

    cudaFuncSetAttribute(dvgo_pers_kernel,
                         cudaFuncAttributeMaxDynamicSharedMemorySize, SMEM_BYTES);
    dvgo_pers_kernel<<<NBLOCKS, 256, SMEM_BYTES>>>(ro, rd, density, k0,
                                                   W0, b0, b1, b2, out, nrays);
}